// round 5
// baseline (speedup 1.0000x reference)
#include <cuda_runtime.h>
#include <cuda_fp16.h>
#include <cstdint>

#define N_USERS 100000
#define N_ITEMS 150000
#define N_NODES (N_USERS + N_ITEMS)
#define N_EDGES 4000000
#define DIM 64

#define SCAN_TB   256
#define SCAN_IPT  4
#define SCAN_TILE (SCAN_TB * SCAN_IPT)                    // 1024
#define N_SCAN_BLOCKS ((N_NODES + SCAN_TILE - 1) / SCAN_TILE)  // 245

// Layer outputs in fp16 (32 MB each) — accumulation stays fp32 in registers.
__device__ __half g_x1[(size_t)N_NODES * DIM];
__device__ __half g_x2[(size_t)N_NODES * DIM];
__device__ __half g_x3[(size_t)N_NODES * DIM];
// CSR machinery
__device__ int  g_cnt[N_NODES];
__device__ int  g_rp[N_NODES + 1];
__device__ int  g_offs[N_NODES];
__device__ int  g_sums[SCAN_TB];
__device__ int2 g_edges[N_EDGES];          // packed {src, val_bits}, sorted by dst

// ---------- histogram: cnt[dst]++ ----------
__global__ void hist_kernel(const int* __restrict__ edst, int* __restrict__ cnt) {
    int i = blockIdx.x * blockDim.x + threadIdx.x;         // edge/4 index
    if (i >= N_EDGES / 4) return;
    int4 d = __ldcs(((const int4*)edst) + i);
    atomicAdd(cnt + d.x, 1);
    atomicAdd(cnt + d.y, 1);
    atomicAdd(cnt + d.z, 1);
    atomicAdd(cnt + d.w, 1);
}

// ---------- exclusive scan, 3 stages ----------
__global__ void scan_blocks(const int* __restrict__ in, int* __restrict__ out,
                            int* __restrict__ sums, int n) {
    __shared__ int wsum[8];
    int tid  = threadIdx.x;
    int base = blockIdx.x * SCAN_TILE + tid * SCAN_IPT;
    int v0 = 0, v1 = 0, v2 = 0, v3 = 0;
    if (base + 3 < n) {
        int4 t = *(const int4*)(in + base);
        v0 = t.x; v1 = t.y; v2 = t.z; v3 = t.w;
    } else {
        if (base     < n) v0 = in[base];
        if (base + 1 < n) v1 = in[base + 1];
        if (base + 2 < n) v2 = in[base + 2];
    }
    int tsum = v0 + v1 + v2 + v3;
    int lane = tid & 31, wid = tid >> 5;
    int inc = tsum;
    #pragma unroll
    for (int o = 1; o < 32; o <<= 1) {
        int t = __shfl_up_sync(0xffffffffu, inc, o);
        if (lane >= o) inc += t;
    }
    if (lane == 31) wsum[wid] = inc;
    __syncthreads();
    if (tid < 8) {
        int w = wsum[tid];
        #pragma unroll
        for (int o = 1; o < 8; o <<= 1) {
            int t = __shfl_up_sync(0xffu, w, o);
            if (tid >= o) w += t;
        }
        wsum[tid] = w;
    }
    __syncthreads();
    int excl = inc - tsum + (wid ? wsum[wid - 1] : 0);
    if (base     < n) out[base]     = excl;
    if (base + 1 < n) out[base + 1] = excl + v0;
    if (base + 2 < n) out[base + 2] = excl + v0 + v1;
    if (base + 3 < n) out[base + 3] = excl + v0 + v1 + v2;
    if (tid == 0) sums[blockIdx.x] = wsum[7];
}

__global__ void scan_sums(int* __restrict__ sums, int nb) {
    __shared__ int wsum[8];
    int tid = threadIdx.x;
    int v = (tid < nb) ? sums[tid] : 0;
    int lane = tid & 31, wid = tid >> 5;
    int inc = v;
    #pragma unroll
    for (int o = 1; o < 32; o <<= 1) {
        int t = __shfl_up_sync(0xffffffffu, inc, o);
        if (lane >= o) inc += t;
    }
    if (lane == 31) wsum[wid] = inc;
    __syncthreads();
    if (tid < 8) {
        int w = wsum[tid];
        #pragma unroll
        for (int o = 1; o < 8; o <<= 1) {
            int t = __shfl_up_sync(0xffu, w, o);
            if (tid >= o) w += t;
        }
        wsum[tid] = w;
    }
    __syncthreads();
    int excl = inc - v + (wid ? wsum[wid - 1] : 0);
    if (tid < nb) sums[tid] = excl;
}

__global__ void scan_add(int* __restrict__ rp, int* __restrict__ offs,
                         const int* __restrict__ sums) {
    int i = blockIdx.x * blockDim.x + threadIdx.x;
    if (i < N_NODES) {
        int v = rp[i] + sums[i >> 10];
        rp[i]   = v;
        offs[i] = v;
    }
    if (i == N_NODES) rp[N_NODES] = N_EDGES;
}

// ---------- scatter edges into dst-sorted packed array ----------
__global__ void scatter_kernel(const int* __restrict__ esrc,
                               const int* __restrict__ edst,
                               const float* __restrict__ ev,
                               int* __restrict__ offs,
                               int2* __restrict__ edges) {
    int i = blockIdx.x * blockDim.x + threadIdx.x;         // edge/4 index
    if (i >= N_EDGES / 4) return;
    int4   s = __ldcs(((const int4*)esrc) + i);
    int4   d = __ldcs(((const int4*)edst) + i);
    float4 w = __ldcs(((const float4*)ev) + i);
    int p0 = atomicAdd(offs + d.x, 1);
    int p1 = atomicAdd(offs + d.y, 1);
    int p2 = atomicAdd(offs + d.z, 1);
    int p3 = atomicAdd(offs + d.w, 1);
    edges[p0] = make_int2(s.x, __float_as_int(w.x));
    edges[p1] = make_int2(s.y, __float_as_int(w.y));
    edges[p2] = make_int2(s.z, __float_as_int(w.z));
    edges[p3] = make_int2(s.w, __float_as_int(w.w));
}

// ---------- layer 1: gather fp32 inputs -> fp16 out ----------
__global__ void __launch_bounds__(256) spmm_l1(
    const int2* __restrict__ edges,
    const int*  __restrict__ rp,
    const float* __restrict__ xU,      // rows [0, N_USERS)
    const float* __restrict__ xI,      // rows [N_USERS, N_NODES)
    __half* __restrict__ y) {
    int node = (int)((blockIdx.x * blockDim.x + threadIdx.x) >> 5);
    int lane = threadIdx.x & 31;
    if (node >= N_NODES) return;
    int e   = __ldg(rp + node);
    int end = __ldg(rp + node + 1);

    float a0x = 0.f, a0y = 0.f, a1x = 0.f, a1y = 0.f;
    float a2x = 0.f, a2y = 0.f, a3x = 0.f, a3y = 0.f;
    const size_t bofs = (size_t)N_USERS * DIM;

    for (; e + 3 < end; e += 4) {
        int2 p0 = __ldg(edges + e);
        int2 p1 = __ldg(edges + e + 1);
        int2 p2 = __ldg(edges + e + 2);
        int2 p3 = __ldg(edges + e + 3);
        const float* b0 = (p0.x < N_USERS) ? xU : (xI - bofs);
        const float* b1 = (p1.x < N_USERS) ? xU : (xI - bofs);
        const float* b2 = (p2.x < N_USERS) ? xU : (xI - bofs);
        const float* b3 = (p3.x < N_USERS) ? xU : (xI - bofs);
        float2 v0 = __ldg(((const float2*)(b0 + (size_t)p0.x * DIM)) + lane);
        float2 v1 = __ldg(((const float2*)(b1 + (size_t)p1.x * DIM)) + lane);
        float2 v2 = __ldg(((const float2*)(b2 + (size_t)p2.x * DIM)) + lane);
        float2 v3 = __ldg(((const float2*)(b3 + (size_t)p3.x * DIM)) + lane);
        float w0 = __int_as_float(p0.y);
        float w1 = __int_as_float(p1.y);
        float w2 = __int_as_float(p2.y);
        float w3 = __int_as_float(p3.y);
        a0x += w0 * v0.x; a0y += w0 * v0.y;
        a1x += w1 * v1.x; a1y += w1 * v1.y;
        a2x += w2 * v2.x; a2y += w2 * v2.y;
        a3x += w3 * v3.x; a3y += w3 * v3.y;
    }
    for (; e < end; ++e) {
        int2 p = __ldg(edges + e);
        const float* b = (p.x < N_USERS) ? xU : (xI - bofs);
        float2 v = __ldg(((const float2*)(b + (size_t)p.x * DIM)) + lane);
        float w = __int_as_float(p.y);
        a0x += w * v.x; a0y += w * v.y;
    }
    float2 o; o.x = (a0x + a1x) + (a2x + a3x); o.y = (a0y + a1y) + (a2y + a3y);
    ((__half2*)(y + (size_t)node * DIM))[lane] = __float22half2_rn(o);
}

// ---------- layers 2/3: gather fp16 -> fp16 out (row = 128B = one L2 line) ----------
__global__ void __launch_bounds__(256) spmm_l(
    const int2* __restrict__ edges,
    const int*  __restrict__ rp,
    const __half* __restrict__ x,
    __half* __restrict__ y) {
    int node = (int)((blockIdx.x * blockDim.x + threadIdx.x) >> 5);
    int lane = threadIdx.x & 31;
    if (node >= N_NODES) return;
    int e   = __ldg(rp + node);
    int end = __ldg(rp + node + 1);

    float a0x = 0.f, a0y = 0.f, a1x = 0.f, a1y = 0.f;
    float a2x = 0.f, a2y = 0.f, a3x = 0.f, a3y = 0.f;

    for (; e + 3 < end; e += 4) {
        int2 p0 = __ldg(edges + e);
        int2 p1 = __ldg(edges + e + 1);
        int2 p2 = __ldg(edges + e + 2);
        int2 p3 = __ldg(edges + e + 3);
        __half2 h0 = __ldg(((const __half2*)(x + (size_t)p0.x * DIM)) + lane);
        __half2 h1 = __ldg(((const __half2*)(x + (size_t)p1.x * DIM)) + lane);
        __half2 h2 = __ldg(((const __half2*)(x + (size_t)p2.x * DIM)) + lane);
        __half2 h3 = __ldg(((const __half2*)(x + (size_t)p3.x * DIM)) + lane);
        float2 v0 = __half22float2(h0);
        float2 v1 = __half22float2(h1);
        float2 v2 = __half22float2(h2);
        float2 v3 = __half22float2(h3);
        float w0 = __int_as_float(p0.y);
        float w1 = __int_as_float(p1.y);
        float w2 = __int_as_float(p2.y);
        float w3 = __int_as_float(p3.y);
        a0x += w0 * v0.x; a0y += w0 * v0.y;
        a1x += w1 * v1.x; a1y += w1 * v1.y;
        a2x += w2 * v2.x; a2y += w2 * v2.y;
        a3x += w3 * v3.x; a3y += w3 * v3.y;
    }
    for (; e < end; ++e) {
        int2 p = __ldg(edges + e);
        float2 v = __half22float2(
            __ldg(((const __half2*)(x + (size_t)p.x * DIM)) + lane));
        float w = __int_as_float(p.y);
        a0x += w * v.x; a0y += w * v.y;
    }
    float2 o; o.x = (a0x + a1x) + (a2x + a3x); o.y = (a0y + a1y) + (a2y + a3y);
    ((__half2*)(y + (size_t)node * DIM))[lane] = __float22half2_rn(o);
}

// ---------- out = (concat(user,item) + x1 + x2 + x3) * 0.25 ----------
__global__ void final_kernel(const float* __restrict__ user_emb,
                             const float* __restrict__ item_emb,
                             const __half* __restrict__ x1,
                             const __half* __restrict__ x2,
                             const __half* __restrict__ x3,
                             float* __restrict__ out) {
    size_t i = (size_t)blockIdx.x * blockDim.x + threadIdx.x;   // float2 index
    const size_t total2 = (size_t)N_NODES * DIM / 2;
    if (i >= total2) return;
    const size_t ub2 = (size_t)N_USERS * DIM / 2;
    float2 e0;
    if (i < ub2) e0 = __ldcs(((const float2*)user_emb) + i);
    else         e0 = __ldcs(((const float2*)item_emb) + (i - ub2));
    float2 a  = __half22float2(__ldcs(((const __half2*)x1) + i));
    float2 b  = __half22float2(__ldcs(((const __half2*)x2) + i));
    float2 cc = __half22float2(__ldcs(((const __half2*)x3) + i));
    float2 o;
    o.x = (e0.x + a.x + b.x + cc.x) * 0.25f;
    o.y = (e0.y + a.y + b.y + cc.y) * 0.25f;
    ((float2*)out)[i] = o;
}

extern "C" void kernel_launch(void* const* d_in, const int* in_sizes, int n_in,
                              void* d_out, int out_size) {
    const float* user_emb = (const float*)d_in[0];
    const float* item_emb = (const float*)d_in[1];
    const float* evals    = (const float*)d_in[2];
    const int*   esrc     = (const int*)  d_in[3];
    const int*   edst     = (const int*)  d_in[4];
    float* out = (float*)d_out;

    __half *x1, *x2, *x3; int *cnt, *rp, *offs, *sums; int2 *edges;
    cudaGetSymbolAddress((void**)&x1,    g_x1);
    cudaGetSymbolAddress((void**)&x2,    g_x2);
    cudaGetSymbolAddress((void**)&x3,    g_x3);
    cudaGetSymbolAddress((void**)&cnt,   g_cnt);
    cudaGetSymbolAddress((void**)&rp,    g_rp);
    cudaGetSymbolAddress((void**)&offs,  g_offs);
    cudaGetSymbolAddress((void**)&sums,  g_sums);
    cudaGetSymbolAddress((void**)&edges, g_edges);

    const int TB = 256;
    const int g_e4   = (N_EDGES / 4 + TB - 1) / TB;
    const int g_node = (N_NODES + 1 + TB - 1) / TB;
    const int g_spmm = (N_NODES * 32 + TB - 1) / TB;
    const int g_fin  = (int)(((size_t)N_NODES * DIM / 2 + TB - 1) / TB);

    // ---- build CSR (counting sort by dst) ----
    cudaMemsetAsync(cnt, 0, N_NODES * sizeof(int));
    hist_kernel<<<g_e4, TB>>>(edst, cnt);
    scan_blocks<<<N_SCAN_BLOCKS, SCAN_TB>>>(cnt, rp, sums, N_NODES);
    scan_sums<<<1, SCAN_TB>>>(sums, N_SCAN_BLOCKS);
    scan_add<<<g_node, TB>>>(rp, offs, sums);
    scatter_kernel<<<g_e4, TB>>>(esrc, edst, evals, offs, edges);

    // ---- 3 gather-only SpMM layers ----
    spmm_l1<<<g_spmm, TB>>>(edges, rp, user_emb, item_emb, x1);
    spmm_l <<<g_spmm, TB>>>(edges, rp, x1, x2);
    spmm_l <<<g_spmm, TB>>>(edges, rp, x2, x3);

    // ---- final combine ----
    final_kernel<<<g_fin, TB>>>(user_emb, item_emb, x1, x2, x3, out);
}

// round 6
// speedup vs baseline: 1.3041x; 1.3041x over previous
#include <cuda_runtime.h>
#include <cstdint>

#define N_USERS 100000
#define N_ITEMS 150000
#define N_NODES (N_USERS + N_ITEMS)
#define N_EDGES 4000000
#define DIM 64

#define SCAN_TB   256
#define SCAN_IPT  4
#define SCAN_TILE (SCAN_TB * SCAN_IPT)                    // 1024
#define N_SCAN_BLOCKS ((N_NODES + SCAN_TILE - 1) / SCAN_TILE)  // 245

// Layer outputs (64 MB each)
__device__ float g_x1[(size_t)N_NODES * DIM];
__device__ float g_x2[(size_t)N_NODES * DIM];
__device__ float g_x3[(size_t)N_NODES * DIM];
// CSR machinery
__device__ int  g_cnt[N_NODES];
__device__ int  g_rp[N_NODES + 1];
__device__ int  g_offs[N_NODES];
__device__ int  g_sums[SCAN_TB];
__device__ int2 g_edges[N_EDGES];          // packed {src, val_bits}, sorted by dst

// ---------- histogram: cnt[dst]++ ----------
__global__ void hist_kernel(const int* __restrict__ edst, int* __restrict__ cnt) {
    int i = blockIdx.x * blockDim.x + threadIdx.x;         // edge/4 index
    if (i >= N_EDGES / 4) return;
    int4 d = __ldcs(((const int4*)edst) + i);
    atomicAdd(cnt + d.x, 1);
    atomicAdd(cnt + d.y, 1);
    atomicAdd(cnt + d.z, 1);
    atomicAdd(cnt + d.w, 1);
}

// ---------- exclusive scan, 3 stages ----------
__global__ void scan_blocks(const int* __restrict__ in, int* __restrict__ out,
                            int* __restrict__ sums, int n) {
    __shared__ int wsum[8];
    int tid  = threadIdx.x;
    int base = blockIdx.x * SCAN_TILE + tid * SCAN_IPT;
    int v0 = 0, v1 = 0, v2 = 0, v3 = 0;
    if (base + 3 < n) {
        int4 t = *(const int4*)(in + base);
        v0 = t.x; v1 = t.y; v2 = t.z; v3 = t.w;
    } else {
        if (base     < n) v0 = in[base];
        if (base + 1 < n) v1 = in[base + 1];
        if (base + 2 < n) v2 = in[base + 2];
    }
    int tsum = v0 + v1 + v2 + v3;
    int lane = tid & 31, wid = tid >> 5;
    int inc = tsum;
    #pragma unroll
    for (int o = 1; o < 32; o <<= 1) {
        int t = __shfl_up_sync(0xffffffffu, inc, o);
        if (lane >= o) inc += t;
    }
    if (lane == 31) wsum[wid] = inc;
    __syncthreads();
    if (tid < 8) {
        int w = wsum[tid];
        #pragma unroll
        for (int o = 1; o < 8; o <<= 1) {
            int t = __shfl_up_sync(0xffu, w, o);
            if (tid >= o) w += t;
        }
        wsum[tid] = w;
    }
    __syncthreads();
    int excl = inc - tsum + (wid ? wsum[wid - 1] : 0);
    if (base     < n) out[base]     = excl;
    if (base + 1 < n) out[base + 1] = excl + v0;
    if (base + 2 < n) out[base + 2] = excl + v0 + v1;
    if (base + 3 < n) out[base + 3] = excl + v0 + v1 + v2;
    if (tid == 0) sums[blockIdx.x] = wsum[7];
}

__global__ void scan_sums(int* __restrict__ sums, int nb) {
    __shared__ int wsum[8];
    int tid = threadIdx.x;
    int v = (tid < nb) ? sums[tid] : 0;
    int lane = tid & 31, wid = tid >> 5;
    int inc = v;
    #pragma unroll
    for (int o = 1; o < 32; o <<= 1) {
        int t = __shfl_up_sync(0xffffffffu, inc, o);
        if (lane >= o) inc += t;
    }
    if (lane == 31) wsum[wid] = inc;
    __syncthreads();
    if (tid < 8) {
        int w = wsum[tid];
        #pragma unroll
        for (int o = 1; o < 8; o <<= 1) {
            int t = __shfl_up_sync(0xffu, w, o);
            if (tid >= o) w += t;
        }
        wsum[tid] = w;
    }
    __syncthreads();
    int excl = inc - v + (wid ? wsum[wid - 1] : 0);
    if (tid < nb) sums[tid] = excl;
}

__global__ void scan_add(int* __restrict__ rp, int* __restrict__ offs,
                         const int* __restrict__ sums) {
    int i = blockIdx.x * blockDim.x + threadIdx.x;
    if (i < N_NODES) {
        int v = rp[i] + sums[i >> 10];
        rp[i]   = v;
        offs[i] = v;
    }
    if (i == N_NODES) rp[N_NODES] = N_EDGES;
}

// ---------- scatter edges into dst-sorted packed array ----------
__global__ void scatter_kernel(const int* __restrict__ esrc,
                               const int* __restrict__ edst,
                               const float* __restrict__ ev,
                               int* __restrict__ offs,
                               int2* __restrict__ edges) {
    int i = blockIdx.x * blockDim.x + threadIdx.x;         // edge/4 index
    if (i >= N_EDGES / 4) return;
    int4   s = __ldcs(((const int4*)esrc) + i);
    int4   d = __ldcs(((const int4*)edst) + i);
    float4 w = __ldcs(((const float4*)ev) + i);
    int p0 = atomicAdd(offs + d.x, 1);
    int p1 = atomicAdd(offs + d.y, 1);
    int p2 = atomicAdd(offs + d.z, 1);
    int p3 = atomicAdd(offs + d.w, 1);
    edges[p0] = make_int2(s.x, __float_as_int(w.x));
    edges[p1] = make_int2(s.y, __float_as_int(w.y));
    edges[p2] = make_int2(s.z, __float_as_int(w.z));
    edges[p3] = make_int2(s.w, __float_as_int(w.w));
}

// ---------- gather-only SpMM: HALF-WARP per dst node, float4 per lane ----------
// 16 lanes x 16B = one 256B row -> one gather LDG instruction services two
// nodes. 4 independent edge chains in flight per half-warp. y stored with .cs
// so the write-once output never evicts the L2-resident x rows + edge array.
// FUSE!=0 additionally does out = (e0 + x1 + x2 + y)*0.25 (layer-3 fusion).
template<int FUSE>
__global__ void __launch_bounds__(256) spmm_csr2(
    const int2* __restrict__ edges,
    const int*  __restrict__ rp,
    const float* __restrict__ xU,      // rows [0, boundary)
    const float* __restrict__ xI,      // rows [boundary, N_NODES)
    int boundary,
    float* __restrict__ y,
    const float* __restrict__ f_u,     // FUSE: user_emb
    const float* __restrict__ f_i,     // FUSE: item_emb
    const float* __restrict__ f_x1,    // FUSE: layer-1 out
    const float* __restrict__ f_x2)    // FUSE: layer-2 out
{
    int w    = (int)((blockIdx.x * blockDim.x + threadIdx.x) >> 5);
    int lane = threadIdx.x & 31;
    int half = lane >> 4;
    int l16  = lane & 15;
    int node = w * 2 + half;
    if (node >= N_NODES) return;

    int e   = __ldg(rp + node);
    int end = __ldg(rp + node + 1);

    float4 a0 = make_float4(0.f, 0.f, 0.f, 0.f);
    float4 a1 = make_float4(0.f, 0.f, 0.f, 0.f);
    float4 a2 = make_float4(0.f, 0.f, 0.f, 0.f);
    float4 a3 = make_float4(0.f, 0.f, 0.f, 0.f);

    const size_t bofs = (size_t)boundary * DIM;

    for (; e + 3 < end; e += 4) {
        int2 p0 = __ldg(edges + e);
        int2 p1 = __ldg(edges + e + 1);
        int2 p2 = __ldg(edges + e + 2);
        int2 p3 = __ldg(edges + e + 3);
        const float* b0 = (p0.x < boundary) ? xU : (xI - bofs);
        const float* b1 = (p1.x < boundary) ? xU : (xI - bofs);
        const float* b2 = (p2.x < boundary) ? xU : (xI - bofs);
        const float* b3 = (p3.x < boundary) ? xU : (xI - bofs);
        float4 v0 = __ldg(((const float4*)(b0 + (size_t)p0.x * DIM)) + l16);
        float4 v1 = __ldg(((const float4*)(b1 + (size_t)p1.x * DIM)) + l16);
        float4 v2 = __ldg(((const float4*)(b2 + (size_t)p2.x * DIM)) + l16);
        float4 v3 = __ldg(((const float4*)(b3 + (size_t)p3.x * DIM)) + l16);
        float w0 = __int_as_float(p0.y);
        float w1 = __int_as_float(p1.y);
        float w2 = __int_as_float(p2.y);
        float w3 = __int_as_float(p3.y);
        a0.x += w0 * v0.x; a0.y += w0 * v0.y; a0.z += w0 * v0.z; a0.w += w0 * v0.w;
        a1.x += w1 * v1.x; a1.y += w1 * v1.y; a1.z += w1 * v1.z; a1.w += w1 * v1.w;
        a2.x += w2 * v2.x; a2.y += w2 * v2.y; a2.z += w2 * v2.z; a2.w += w2 * v2.w;
        a3.x += w3 * v3.x; a3.y += w3 * v3.y; a3.z += w3 * v3.z; a3.w += w3 * v3.w;
    }
    for (; e < end; ++e) {
        int2 p = __ldg(edges + e);
        const float* b = (p.x < boundary) ? xU : (xI - bofs);
        float4 v = __ldg(((const float4*)(b + (size_t)p.x * DIM)) + l16);
        float ww = __int_as_float(p.y);
        a0.x += ww * v.x; a0.y += ww * v.y; a0.z += ww * v.z; a0.w += ww * v.w;
    }
    float4 o;
    o.x = (a0.x + a1.x) + (a2.x + a3.x);
    o.y = (a0.y + a1.y) + (a2.y + a3.y);
    o.z = (a0.z + a1.z) + (a2.z + a3.z);
    o.w = (a0.w + a1.w) + (a2.w + a3.w);

    if (FUSE) {
        // out = (e0 + x1 + x2 + x3) * 0.25, e0 from split inputs
        const size_t ro = (size_t)node * DIM + (size_t)l16 * 4;
        float4 e0;
        if (node < N_USERS)
            e0 = __ldcs((const float4*)(f_u + ro));
        else
            e0 = __ldcs((const float4*)(f_i + ro - (size_t)N_USERS * DIM));
        float4 q1 = __ldcs((const float4*)(f_x1 + ro));
        float4 q2 = __ldcs((const float4*)(f_x2 + ro));
        o.x = (e0.x + q1.x + q2.x + o.x) * 0.25f;
        o.y = (e0.y + q1.y + q2.y + o.y) * 0.25f;
        o.z = (e0.z + q1.z + q2.z + o.z) * 0.25f;
        o.w = (e0.w + q1.w + q2.w + o.w) * 0.25f;
        float* p = y + ro;
        asm volatile("st.global.cs.v4.f32 [%0], {%1, %2, %3, %4};"
                     :: "l"(p), "f"(o.x), "f"(o.y), "f"(o.z), "f"(o.w)
                     : "memory");
    } else {
        float* p = y + (size_t)node * DIM + (size_t)l16 * 4;
        asm volatile("st.global.cs.v4.f32 [%0], {%1, %2, %3, %4};"
                     :: "l"(p), "f"(o.x), "f"(o.y), "f"(o.z), "f"(o.w)
                     : "memory");
    }
}

extern "C" void kernel_launch(void* const* d_in, const int* in_sizes, int n_in,
                              void* d_out, int out_size) {
    const float* user_emb = (const float*)d_in[0];
    const float* item_emb = (const float*)d_in[1];
    const float* evals    = (const float*)d_in[2];
    const int*   esrc     = (const int*)  d_in[3];
    const int*   edst     = (const int*)  d_in[4];
    float* out = (float*)d_out;

    float *x1, *x2, *x3; int *cnt, *rp, *offs, *sums; int2 *edges;
    cudaGetSymbolAddress((void**)&x1,    g_x1);
    cudaGetSymbolAddress((void**)&x2,    g_x2);
    cudaGetSymbolAddress((void**)&x3,    g_x3);
    cudaGetSymbolAddress((void**)&cnt,   g_cnt);
    cudaGetSymbolAddress((void**)&rp,    g_rp);
    cudaGetSymbolAddress((void**)&offs,  g_offs);
    cudaGetSymbolAddress((void**)&sums,  g_sums);
    cudaGetSymbolAddress((void**)&edges, g_edges);

    const int TB = 256;
    const int g_e4   = (N_EDGES / 4 + TB - 1) / TB;
    const int g_node = (N_NODES + 1 + TB - 1) / TB;
    // half-warp per node: N_NODES/2 warps
    const int g_spmm = (int)(((size_t)(N_NODES / 2) * 32 + TB - 1) / TB);

    // ---- build CSR (counting sort by dst) ----
    cudaMemsetAsync(cnt, 0, N_NODES * sizeof(int));
    hist_kernel<<<g_e4, TB>>>(edst, cnt);
    scan_blocks<<<N_SCAN_BLOCKS, SCAN_TB>>>(cnt, rp, sums, N_NODES);
    scan_sums<<<1, SCAN_TB>>>(sums, N_SCAN_BLOCKS);
    scan_add<<<g_node, TB>>>(rp, offs, sums);
    scatter_kernel<<<g_e4, TB>>>(esrc, edst, evals, offs, edges);

    // ---- 3 gather-only SpMM layers (layer 3 fused with final combine) ----
    spmm_csr2<0><<<g_spmm, TB>>>(edges, rp, user_emb, item_emb, N_USERS, x1,
                                 nullptr, nullptr, nullptr, nullptr);
    spmm_csr2<0><<<g_spmm, TB>>>(edges, rp, x1, x1, N_NODES, x2,
                                 nullptr, nullptr, nullptr, nullptr);
    spmm_csr2<1><<<g_spmm, TB>>>(edges, rp, x2, x2, N_NODES, out,
                                 user_emb, item_emb, x1, x2);
}

// round 7
// speedup vs baseline: 1.3613x; 1.0439x over previous
#include <cuda_runtime.h>
#include <cuda_fp16.h>
#include <cstdint>

#define N_USERS 100000
#define N_ITEMS 150000
#define N_NODES (N_USERS + N_ITEMS)
#define N_EDGES 4000000
#define DIM 64

#define SCAN_TB   256
#define SCAN_IPT  4
#define SCAN_TILE (SCAN_TB * SCAN_IPT)                    // 1024
#define N_SCAN_BLOCKS ((N_NODES + SCAN_TILE - 1) / SCAN_TILE)  // 245

// fp16 embeddings: x0 = quantized inputs, x1/x2 = layer outputs (32 MB each)
__device__ __half g_x0[(size_t)N_NODES * DIM];
__device__ __half g_x1[(size_t)N_NODES * DIM];
__device__ __half g_x2[(size_t)N_NODES * DIM];
// CSR machinery (g_cnt zero-initialized at module load; scan_add re-zeroes it
// every launch after scan_blocks has consumed it -> invariant: cnt==0 at entry)
__device__ int  g_cnt[N_NODES];
__device__ int  g_rp[N_NODES + 1];
__device__ int  g_offs[N_NODES];
__device__ int  g_sums[SCAN_TB];
__device__ int2 g_edges[N_EDGES];          // packed {src, val_bits}, sorted by dst

// ---------- convert fp32 inputs -> fp16 x0 ----------
__global__ void convert_kernel(const float* __restrict__ user_emb,
                               const float* __restrict__ item_emb,
                               __half* __restrict__ x0) {
    size_t i = (size_t)blockIdx.x * blockDim.x + threadIdx.x;  // half2 index
    const size_t total2 = (size_t)N_NODES * DIM / 2;
    if (i >= total2) return;
    const size_t ub2 = (size_t)N_USERS * DIM / 2;
    float2 v;
    if (i < ub2) v = __ldcs(((const float2*)user_emb) + i);
    else         v = __ldcs(((const float2*)item_emb) + (i - ub2));
    ((__half2*)x0)[i] = __float22half2_rn(v);
}

// ---------- histogram: cnt[dst]++ ----------
__global__ void hist_kernel(const int* __restrict__ edst, int* __restrict__ cnt) {
    int i = blockIdx.x * blockDim.x + threadIdx.x;         // edge/4 index
    if (i >= N_EDGES / 4) return;
    int4 d = __ldcs(((const int4*)edst) + i);
    atomicAdd(cnt + d.x, 1);
    atomicAdd(cnt + d.y, 1);
    atomicAdd(cnt + d.z, 1);
    atomicAdd(cnt + d.w, 1);
}

// ---------- exclusive scan, 3 stages ----------
__global__ void scan_blocks(const int* __restrict__ in, int* __restrict__ out,
                            int* __restrict__ sums, int n) {
    __shared__ int wsum[8];
    int tid  = threadIdx.x;
    int base = blockIdx.x * SCAN_TILE + tid * SCAN_IPT;
    int v0 = 0, v1 = 0, v2 = 0, v3 = 0;
    if (base + 3 < n) {
        int4 t = *(const int4*)(in + base);
        v0 = t.x; v1 = t.y; v2 = t.z; v3 = t.w;
    } else {
        if (base     < n) v0 = in[base];
        if (base + 1 < n) v1 = in[base + 1];
        if (base + 2 < n) v2 = in[base + 2];
    }
    int tsum = v0 + v1 + v2 + v3;
    int lane = tid & 31, wid = tid >> 5;
    int inc = tsum;
    #pragma unroll
    for (int o = 1; o < 32; o <<= 1) {
        int t = __shfl_up_sync(0xffffffffu, inc, o);
        if (lane >= o) inc += t;
    }
    if (lane == 31) wsum[wid] = inc;
    __syncthreads();
    if (tid < 8) {
        int w = wsum[tid];
        #pragma unroll
        for (int o = 1; o < 8; o <<= 1) {
            int t = __shfl_up_sync(0xffu, w, o);
            if (tid >= o) w += t;
        }
        wsum[tid] = w;
    }
    __syncthreads();
    int excl = inc - tsum + (wid ? wsum[wid - 1] : 0);
    if (base     < n) out[base]     = excl;
    if (base + 1 < n) out[base + 1] = excl + v0;
    if (base + 2 < n) out[base + 2] = excl + v0 + v1;
    if (base + 3 < n) out[base + 3] = excl + v0 + v1 + v2;
    if (tid == 0) sums[blockIdx.x] = wsum[7];
}

__global__ void scan_sums(int* __restrict__ sums, int nb) {
    __shared__ int wsum[8];
    int tid = threadIdx.x;
    int v = (tid < nb) ? sums[tid] : 0;
    int lane = tid & 31, wid = tid >> 5;
    int inc = v;
    #pragma unroll
    for (int o = 1; o < 32; o <<= 1) {
        int t = __shfl_up_sync(0xffffffffu, inc, o);
        if (lane >= o) inc += t;
    }
    if (lane == 31) wsum[wid] = inc;
    __syncthreads();
    if (tid < 8) {
        int w = wsum[tid];
        #pragma unroll
        for (int o = 1; o < 8; o <<= 1) {
            int t = __shfl_up_sync(0xffu, w, o);
            if (tid >= o) w += t;
        }
        wsum[tid] = w;
    }
    __syncthreads();
    int excl = inc - v + (wid ? wsum[wid - 1] : 0);
    if (tid < nb) sums[tid] = excl;
}

__global__ void scan_add(int* __restrict__ rp, int* __restrict__ offs,
                         const int* __restrict__ sums, int* __restrict__ cnt) {
    int i = blockIdx.x * blockDim.x + threadIdx.x;
    if (i < N_NODES) {
        int v = rp[i] + sums[i >> 10];
        rp[i]   = v;
        offs[i] = v;
        cnt[i]  = 0;                 // reset for next launch (invariant)
    }
    if (i == N_NODES) rp[N_NODES] = N_EDGES;
}

// ---------- scatter edges into dst-sorted packed array ----------
__global__ void scatter_kernel(const int* __restrict__ esrc,
                               const int* __restrict__ edst,
                               const float* __restrict__ ev,
                               int* __restrict__ offs,
                               int2* __restrict__ edges) {
    int i = blockIdx.x * blockDim.x + threadIdx.x;         // edge/4 index
    if (i >= N_EDGES / 4) return;
    int4   s = __ldcs(((const int4*)esrc) + i);
    int4   d = __ldcs(((const int4*)edst) + i);
    float4 w = __ldcs(((const float4*)ev) + i);
    int p0 = atomicAdd(offs + d.x, 1);
    int p1 = atomicAdd(offs + d.y, 1);
    int p2 = atomicAdd(offs + d.z, 1);
    int p3 = atomicAdd(offs + d.w, 1);
    edges[p0] = make_int2(s.x, __float_as_int(w.x));
    edges[p1] = make_int2(s.y, __float_as_int(w.y));
    edges[p2] = make_int2(s.z, __float_as_int(w.z));
    edges[p3] = make_int2(s.w, __float_as_int(w.w));
}

// ---------- gather-only SpMM on fp16 rows: warp per node, half2 per lane ----
// fp16 row = 128B = one wavefront per edge gather. fp32 accumulation.
// 4 independent edge chains. Outputs stored with .cs (write-once here).
// FUSE!=0: out = (e0_fp32 + x1 + x2 + acc) * 0.25 written fp32 to d_out.
template<int FUSE>
__global__ void __launch_bounds__(256) spmm_f16(
    const int2*   __restrict__ edges,
    const int*    __restrict__ rp,
    const __half* __restrict__ x,
    __half*       __restrict__ y,      // !FUSE
    const float*  __restrict__ f_u,    // FUSE: user_emb
    const float*  __restrict__ f_i,    // FUSE: item_emb
    const __half* __restrict__ f_x1,   // FUSE
    const __half* __restrict__ f_x2,   // FUSE
    float*        __restrict__ fout)   // FUSE
{
    int node = (int)((blockIdx.x * blockDim.x + threadIdx.x) >> 5);
    int lane = threadIdx.x & 31;
    if (node >= N_NODES) return;

    int e   = __ldg(rp + node);
    int end = __ldg(rp + node + 1);

    float a0x = 0.f, a0y = 0.f, a1x = 0.f, a1y = 0.f;
    float a2x = 0.f, a2y = 0.f, a3x = 0.f, a3y = 0.f;

    for (; e + 3 < end; e += 4) {
        int2 p0 = __ldg(edges + e);
        int2 p1 = __ldg(edges + e + 1);
        int2 p2 = __ldg(edges + e + 2);
        int2 p3 = __ldg(edges + e + 3);
        float2 v0 = __half22float2(__ldg(((const __half2*)(x + (size_t)p0.x * DIM)) + lane));
        float2 v1 = __half22float2(__ldg(((const __half2*)(x + (size_t)p1.x * DIM)) + lane));
        float2 v2 = __half22float2(__ldg(((const __half2*)(x + (size_t)p2.x * DIM)) + lane));
        float2 v3 = __half22float2(__ldg(((const __half2*)(x + (size_t)p3.x * DIM)) + lane));
        float w0 = __int_as_float(p0.y);
        float w1 = __int_as_float(p1.y);
        float w2 = __int_as_float(p2.y);
        float w3 = __int_as_float(p3.y);
        a0x += w0 * v0.x; a0y += w0 * v0.y;
        a1x += w1 * v1.x; a1y += w1 * v1.y;
        a2x += w2 * v2.x; a2y += w2 * v2.y;
        a3x += w3 * v3.x; a3y += w3 * v3.y;
    }
    for (; e < end; ++e) {
        int2 p = __ldg(edges + e);
        float2 v = __half22float2(__ldg(((const __half2*)(x + (size_t)p.x * DIM)) + lane));
        float w = __int_as_float(p.y);
        a0x += w * v.x; a0y += w * v.y;
    }
    float ox = (a0x + a1x) + (a2x + a3x);
    float oy = (a0y + a1y) + (a2y + a3y);

    const size_t ro = (size_t)node * DIM + (size_t)lane * 2;
    if (FUSE) {
        float2 e0;
        if (node < N_USERS) e0 = __ldcs((const float2*)(f_u + ro));
        else                e0 = __ldcs((const float2*)(f_i + ro - (size_t)N_USERS * DIM));
        float2 q1 = __half22float2(__ldg(((const __half2*)f_x1) + (ro >> 1)));
        float2 q2 = __half22float2(__ldg(((const __half2*)f_x2) + (ro >> 1)));
        float rx = (e0.x + q1.x + q2.x + ox) * 0.25f;
        float ry = (e0.y + q1.y + q2.y + oy) * 0.25f;
        float* p = fout + ro;
        asm volatile("st.global.cs.v2.f32 [%0], {%1, %2};"
                     :: "l"(p), "f"(rx), "f"(ry) : "memory");
    } else {
        __half2 h = __float22half2_rn(make_float2(ox, oy));
        unsigned hu = *reinterpret_cast<unsigned*>(&h);
        __half* p = y + ro;
        asm volatile("st.global.cs.b32 [%0], %1;"
                     :: "l"(p), "r"(hu) : "memory");
    }
}

extern "C" void kernel_launch(void* const* d_in, const int* in_sizes, int n_in,
                              void* d_out, int out_size) {
    const float* user_emb = (const float*)d_in[0];
    const float* item_emb = (const float*)d_in[1];
    const float* evals    = (const float*)d_in[2];
    const int*   esrc     = (const int*)  d_in[3];
    const int*   edst     = (const int*)  d_in[4];
    float* out = (float*)d_out;

    __half *x0, *x1, *x2; int *cnt, *rp, *offs, *sums; int2 *edges;
    cudaGetSymbolAddress((void**)&x0,    g_x0);
    cudaGetSymbolAddress((void**)&x1,    g_x1);
    cudaGetSymbolAddress((void**)&x2,    g_x2);
    cudaGetSymbolAddress((void**)&cnt,   g_cnt);
    cudaGetSymbolAddress((void**)&rp,    g_rp);
    cudaGetSymbolAddress((void**)&offs,  g_offs);
    cudaGetSymbolAddress((void**)&sums,  g_sums);
    cudaGetSymbolAddress((void**)&edges, g_edges);

    const int TB = 256;
    const int g_e4   = (N_EDGES / 4 + TB - 1) / TB;
    const int g_node = (N_NODES + 1 + TB - 1) / TB;
    const int g_cvt  = (int)(((size_t)N_NODES * DIM / 2 + TB - 1) / TB);
    const int g_spmm = (int)(((size_t)N_NODES * 32 + TB - 1) / TB);

    // ---- inputs -> fp16 x0 (independent of CSR build) ----
    convert_kernel<<<g_cvt, TB>>>(user_emb, item_emb, x0);

    // ---- build CSR (counting sort by dst); cnt was zeroed by prior launch ----
    hist_kernel<<<g_e4, TB>>>(edst, cnt);
    scan_blocks<<<N_SCAN_BLOCKS, SCAN_TB>>>(cnt, rp, sums, N_NODES);
    scan_sums<<<1, SCAN_TB>>>(sums, N_SCAN_BLOCKS);
    scan_add<<<g_node, TB>>>(rp, offs, sums, cnt);
    scatter_kernel<<<g_e4, TB>>>(esrc, edst, evals, offs, edges);

    // ---- 3 gather-only SpMM layers (layer 3 fused with final combine) ----
    spmm_f16<0><<<g_spmm, TB>>>(edges, rp, x0, x1,
                                nullptr, nullptr, nullptr, nullptr, nullptr);
    spmm_f16<0><<<g_spmm, TB>>>(edges, rp, x1, x2,
                                nullptr, nullptr, nullptr, nullptr, nullptr);
    spmm_f16<1><<<g_spmm, TB>>>(edges, rp, x2, nullptr,
                                user_emb, item_emb, x1, x2, out);
}